// round 5
// baseline (speedup 1.0000x reference)
#include <cuda_runtime.h>
#include <math.h>

// ---------------------------------------------------------------------------
// GRU: T=512, B=1024, H=128.  out[b] = (h_T @ w_out^T + b_out)
//
// Phase 1 (xg_kernel):  g_xg[t][b][g] = sum_k input[t][b][k]*w_ih[g][k] + b_ih[g]
// Phase 2 (gru_kernel): 512 sequential steps; each CTA owns 8 batch rows,
//                       w_hh lives in SMEM, h lives in SMEM(+regs).
// All heavy math uses packed fma.rn.f32x2 (FFMA2) over batch pairs.
// ---------------------------------------------------------------------------

typedef unsigned long long u64;

static __device__ __forceinline__ u64 pack2(float lo, float hi) {
    u64 r; asm("mov.b64 %0, {%1, %2};" : "=l"(r) : "f"(lo), "f"(hi)); return r;
}
static __device__ __forceinline__ void unpack2(u64 v, float& lo, float& hi) {
    asm("mov.b64 {%0, %1}, %2;" : "=f"(lo), "=f"(hi) : "l"(v));
}
static __device__ __forceinline__ u64 ffma2(u64 a, u64 b, u64 c) {
    u64 d; asm("fma.rn.f32x2 %0, %1, %2, %3;" : "=l"(d) : "l"(a), "l"(b), "l"(c)); return d;
}
static __device__ __forceinline__ float sigf(float x) {
    return __fdividef(1.0f, 1.0f + __expf(-x));
}
static __device__ __forceinline__ float tanhf_fast(float x) {
    float ax = fabsf(x);
    float e  = __expf(-2.0f * ax);
    float t  = __fdividef(1.0f - e, 1.0f + e);
    return copysignf(t, x);
}

constexpr int H  = 128;
constexpr int G  = 384;   // 3*H
constexpr int TT = 512;
constexpr int BB = 1024;
constexpr int WP = 385;   // padded pitch for transposed weights (conflict-free)

// scratch for precomputed input gates: [T][B][3H]  (~805 MB, static device mem)
__device__ float g_xg[(size_t)TT * BB * G];

// ---------------------------------------------------------------------------
// Phase 1: xg = input @ w_ih^T + b_ih
// grid = (T*B)/64 CTAs, 128 threads. Each CTA: 64 rows.
// SMEM: w_sh[128][385] floats (197120 B) + xp u64[128][33] (33792 B) = 230912 B
// ---------------------------------------------------------------------------
constexpr int SMEM1 = H * WP * 4 + H * 33 * 8;

__global__ void __launch_bounds__(128) xg_kernel(const float* __restrict__ input,
                                                 const float* __restrict__ w_ih,
                                                 const float* __restrict__ b_ih) {
    extern __shared__ char smem[];
    float* w_sh = (float*)smem;                       // [k][g], pitch WP
    u64*   xp   = (u64*)(smem + (size_t)H * WP * 4);  // [k][pair], pitch 33

    const int u = threadIdx.x;

    // load w_ih transposed into smem: w_sh[k*WP + g] = w_ih[g*H + k]
    for (int i = u; i < G * H; i += 128) {
        int g = i >> 7, k = i & 127;
        w_sh[k * WP + g] = w_ih[i];
    }

    // load 64 input rows as batch-pairs: xp[k][pglob] = (x[2p][k], x[2p+1][k])
    const size_t m0  = (size_t)blockIdx.x * 64;
    const float* in0 = input + m0 * H;
    #pragma unroll
    for (int rb = 0; rb < 8; rb++) {
        float v[8];
        #pragma unroll
        for (int r = 0; r < 8; r++) v[r] = in0[(size_t)(rb * 8 + r) * H + u];
        #pragma unroll
        for (int p = 0; p < 4; p++)
            xp[u * 33 + rb * 4 + p] = pack2(v[2 * p], v[2 * p + 1]);
    }
    __syncthreads();

    const float br = b_ih[u], bz = b_ih[u + 128], bn = b_ih[u + 256];

    for (int rb = 0; rb < 8; rb++) {
        u64 ar[4] = {0,0,0,0}, az[4] = {0,0,0,0}, an[4] = {0,0,0,0};
        #pragma unroll 8
        for (int k = 0; k < H; k++) {
            float wr = w_sh[k * WP + u];
            float wz = w_sh[k * WP + u + 128];
            float wn = w_sh[k * WP + u + 256];
            u64 wr2 = pack2(wr, wr), wz2 = pack2(wz, wz), wn2 = pack2(wn, wn);
            #pragma unroll
            for (int p = 0; p < 4; p++) {
                u64 x2 = xp[k * 33 + rb * 4 + p];
                ar[p] = ffma2(x2, wr2, ar[p]);
                az[p] = ffma2(x2, wz2, az[p]);
                an[p] = ffma2(x2, wn2, an[p]);
            }
        }
        float* out = g_xg + (m0 + (size_t)rb * 8) * G;
        #pragma unroll
        for (int p = 0; p < 4; p++) {
            float r0, r1, z0, z1, n0, n1;
            unpack2(ar[p], r0, r1); unpack2(az[p], z0, z1); unpack2(an[p], n0, n1);
            out[(size_t)(2 * p)     * G + u      ] = r0 + br;
            out[(size_t)(2 * p + 1) * G + u      ] = r1 + br;
            out[(size_t)(2 * p)     * G + u + 128] = z0 + bz;
            out[(size_t)(2 * p + 1) * G + u + 128] = z1 + bz;
            out[(size_t)(2 * p)     * G + u + 256] = n0 + bn;
            out[(size_t)(2 * p + 1) * G + u + 256] = n1 + bn;
        }
    }
}

// ---------------------------------------------------------------------------
// Phase 2: sequential GRU recurrence + output projection.
// grid = 128 CTAs (8 batch rows each), 128 threads (thread u = hidden unit u).
// SMEM: w_sh[128][385] (197120 B) + hp u64[128][5] (5120 B) + red[8][128] f32
// ---------------------------------------------------------------------------
constexpr int SMEM2 = H * WP * 4 + H * 5 * 8 + 8 * H * 4;

__global__ void __launch_bounds__(128) gru_kernel(const float* __restrict__ initial_h,
                                                  const float* __restrict__ w_hh,
                                                  const float* __restrict__ b_hh,
                                                  const float* __restrict__ w_out,
                                                  const float* __restrict__ b_out,
                                                  float* __restrict__ out) {
    extern __shared__ char smem[];
    float* w_sh = (float*)smem;                                   // [k][g] pitch WP
    u64*   hp   = (u64*)(smem + (size_t)H * WP * 4);              // [k][pair] pitch 5
    float* red  = (float*)(smem + (size_t)H * WP * 4 + H * 5 * 8);// [8][128]

    const int u  = threadIdx.x;
    const int b0 = blockIdx.x * 8;

    // w_hh transposed into smem
    for (int i = u; i < G * H; i += 128) {
        int g = i >> 7, k = i & 127;
        w_sh[k * WP + g] = w_hh[i];
    }

    // initial h: both in smem (for the matvec broadcast) and in regs (h_old)
    u64 hreg[4];
    #pragma unroll
    for (int p = 0; p < 4; p++) {
        float lo = initial_h[(size_t)(b0 + 2 * p)     * H + u];
        float hi = initial_h[(size_t)(b0 + 2 * p + 1) * H + u];
        hreg[p] = pack2(lo, hi);
        hp[u * 5 + p] = hreg[p];
    }
    const float br = b_hh[u], bz = b_hh[u + 128], bn = b_hh[u + 256];
    __syncthreads();

    for (int t = 0; t < TT; t++) {
        // fetch this step's precomputed input gates (8 rows x 3 gates)
        const float* xg = g_xg + ((size_t)t * BB + b0) * G;
        float xr[8], xz[8], xn[8];
        #pragma unroll
        for (int r = 0; r < 8; r++) {
            xr[r] = xg[(size_t)r * G + u];
            xz[r] = xg[(size_t)r * G + u + 128];
            xn[r] = xg[(size_t)r * G + u + 256];
        }

        // hg = h @ w_hh^T  for this thread's 3 gate units, 4 batch pairs
        u64 ar[4] = {0,0,0,0}, az[4] = {0,0,0,0}, an[4] = {0,0,0,0};
        #pragma unroll 8
        for (int k = 0; k < H; k++) {
            float wr = w_sh[k * WP + u];
            float wz = w_sh[k * WP + u + 128];
            float wn = w_sh[k * WP + u + 256];
            u64 wr2 = pack2(wr, wr), wz2 = pack2(wz, wz), wn2 = pack2(wn, wn);
            #pragma unroll
            for (int p = 0; p < 4; p++) {
                u64 h2 = hp[k * 5 + p];            // broadcast across warp
                ar[p] = ffma2(h2, wr2, ar[p]);
                az[p] = ffma2(h2, wz2, az[p]);
                an[p] = ffma2(h2, wn2, an[p]);
            }
        }

        // gates + state update (thread u owns unit u; no cross-thread comm)
        #pragma unroll
        for (int p = 0; p < 4; p++) {
            float hr0, hr1, hz0, hz1, hn0, hn1, ho0, ho1;
            unpack2(ar[p], hr0, hr1);
            unpack2(az[p], hz0, hz1);
            unpack2(an[p], hn0, hn1);
            unpack2(hreg[p], ho0, ho1);

            float r0 = sigf(xr[2 * p] + hr0 + br);
            float z0 = sigf(xz[2 * p] + hz0 + bz);
            float n0 = tanhf_fast(xn[2 * p] + r0 * (hn0 + bn));
            float h0 = (1.0f - z0) * n0 + z0 * ho0;

            float r1 = sigf(xr[2 * p + 1] + hr1 + br);
            float z1 = sigf(xz[2 * p + 1] + hz1 + bz);
            float n1 = tanhf_fast(xn[2 * p + 1] + r1 * (hn1 + bn));
            float h1 = (1.0f - z1) * n1 + z1 * ho1;

            hreg[p] = pack2(h0, h1);
        }

        __syncthreads();                   // all reads of hp done
        #pragma unroll
        for (int p = 0; p < 4; p++) hp[u * 5 + p] = hreg[p];
        __syncthreads();                   // new h visible
    }

    // epilogue: out[b] = sum_u h[b][u] * w_out[u] + b_out  (deterministic tree)
    const float wo = w_out[u];
    #pragma unroll
    for (int p = 0; p < 4; p++) {
        float lo, hi; unpack2(hreg[p], lo, hi);
        red[(2 * p)     * 128 + u] = lo * wo;
        red[(2 * p + 1) * 128 + u] = hi * wo;
    }
    __syncthreads();
    for (int s = 64; s > 0; s >>= 1) {
        if (u < s) {
            #pragma unroll
            for (int r = 0; r < 8; r++) red[r * 128 + u] += red[r * 128 + u + s];
        }
        __syncthreads();
    }
    if (u < 8) out[b0 + u] = red[u * 128] + b_out[0];
}

// ---------------------------------------------------------------------------
// launch
// ---------------------------------------------------------------------------
extern "C" void kernel_launch(void* const* d_in, const int* in_sizes, int n_in,
                              void* d_out, int out_size) {
    const float* input     = (const float*)d_in[0];   // [T, B, H]
    const float* initial_h = (const float*)d_in[1];   // [B, H]
    const float* w_ih      = (const float*)d_in[2];   // [3H, H]
    const float* w_hh      = (const float*)d_in[3];   // [3H, H]
    const float* b_ih      = (const float*)d_in[4];   // [3H]
    const float* b_hh      = (const float*)d_in[5];   // [3H]
    const float* w_out     = (const float*)d_in[6];   // [1, H]
    const float* b_out     = (const float*)d_in[7];   // [1]
    float*       out       = (float*)d_out;           // [B, 1]

    (void)in_sizes; (void)n_in; (void)out_size;

    // opt-in smem (idempotent; safe to call every time, also under capture)
    cudaFuncSetAttribute(xg_kernel,  cudaFuncAttributeMaxDynamicSharedMemorySize, SMEM1);
    cudaFuncSetAttribute(gru_kernel, cudaFuncAttributeMaxDynamicSharedMemorySize, SMEM2);

    // phase 1: all input-to-hidden GEMMs
    xg_kernel<<<(TT * BB) / 64, 128, SMEM1>>>(input, w_ih, b_ih);

    // phase 2: recurrence + projection
    gru_kernel<<<BB / 8, 128, SMEM2>>>(initial_h, w_hh, b_hh, w_out, b_out, out);
}

// round 6
// speedup vs baseline: 1.4232x; 1.4232x over previous
#include <cuda_runtime.h>
#include <math.h>
#include <stdint.h>

// ---------------------------------------------------------------------------
// GRU: T=512, B=1024, H=128.  out = h_T @ w_out^T + b_out
//
// f32x2 (FFMA2) with the SIMD lane over K-PAIRS:
//   acc64 holds (sum over even k, sum over odd k); both operands of every
//   ffma2 come straight from shared memory via ld.shared.v2.u64 — no packing.
//
// Phase 1: persistent 148 CTAs x 512 threads (4 warps/SMSP), weights in smem
//          once per SM, 32-row input tiles double-buffered via registers.
// Phase 2: 128 CTAs x 256 threads (2 warps/SMSP), w_hh + h in smem,
//          xg prefetched one step ahead, biases folded into acc init.
// ---------------------------------------------------------------------------

typedef unsigned long long u64;

static __device__ __forceinline__ u64 pack2(float lo, float hi) {
    u64 r; asm("mov.b64 %0, {%1, %2};" : "=l"(r) : "f"(lo), "f"(hi)); return r;
}
static __device__ __forceinline__ void unpack2(u64 v, float& lo, float& hi) {
    asm("mov.b64 {%0, %1}, %2;" : "=f"(lo), "=f"(hi) : "l"(v));
}
static __device__ __forceinline__ u64 ffma2(u64 a, u64 b, u64 c) {
    u64 d; asm("fma.rn.f32x2 %0, %1, %2, %3;" : "=l"(d) : "l"(a), "l"(b), "l"(c)); return d;
}
static __device__ __forceinline__ void lds_v2u64(u64& a, u64& b, uint32_t addr) {
    asm volatile("ld.shared.v2.u64 {%0, %1}, [%2];" : "=l"(a), "=l"(b) : "r"(addr));
}
static __device__ __forceinline__ uint32_t smem_u32(const void* p) {
    uint32_t a;
    asm("{ .reg .u64 t; cvta.to.shared.u64 t, %1; cvt.u32.u64 %0, t; }" : "=r"(a) : "l"(p));
    return a;
}
static __device__ __forceinline__ float sigf(float x) {
    return __fdividef(1.0f, 1.0f + __expf(-x));
}
static __device__ __forceinline__ float tanhf_fast(float x) {
    float ax = fabsf(x);
    float e  = __expf(-2.0f * ax);
    float t  = __fdividef(1.0f - e, 1.0f + e);
    return copysignf(t, x);
}

constexpr int H  = 128;
constexpr int G  = 384;    // 3*H
constexpr int TT = 512;
constexpr int BB = 1024;

// precomputed input gates: [T*B][3H]  (~805 MB static device scratch)
__device__ float g_xg[(size_t)TT * BB * G];

// shared weight tile: ws4[kk][g] (kk = k/4, 4 k-values per float4), 32*384*16 B
constexpr int WS_BYTES = 32 * G * 16;      // 196608
constexpr int XS_PITCH = 132;              // float pitch per row (16B-aligned, low-conflict)

// ---------------------------------------------------------------------------
// Phase 1: g_xg = input @ w_ih^T + b_ih   (persistent GEMM)
// ---------------------------------------------------------------------------
constexpr int ROWS1 = 32;
constexpr int THR1  = 512;
constexpr int NBLK1 = (TT * BB) / ROWS1;   // 16384 tiles
constexpr int GRID1 = 148;
constexpr int SMEM1 = WS_BYTES + ROWS1 * XS_PITCH * 4;   // 213504 B

__global__ void __launch_bounds__(THR1) xg_kernel(const float* __restrict__ input,
                                                  const float* __restrict__ w_ih,
                                                  const float* __restrict__ b_ih) {
    extern __shared__ char smem[];
    float4* ws4 = (float4*)smem;
    float*  xs  = (float*)(smem + WS_BYTES);
    const uint32_t ws_a = smem_u32(smem);
    const uint32_t xs_a = ws_a + WS_BYTES;

    const int tid = threadIdx.x;
    const int u   = tid & 127;      // gate unit (gates u, u+128, u+256)
    const int s   = tid >> 7;       // row octet: rows s*8 .. s*8+7

    // stage weights once: ws4[kk*384 + g] = w_ih[g][4kk..4kk+3]
    const float4* w4 = (const float4*)w_ih;
    for (int i = tid; i < G * 32; i += THR1) {
        int g = i >> 5, kk = i & 31;
        ws4[kk * G + g] = w4[g * 32 + kk];
    }
    const float br = b_ih[u], bz = b_ih[u + 128], bn = b_ih[u + 256];

    const int r_st = tid >> 5, kq = tid & 31;   // staging map
    int j = blockIdx.x;
    float4 pf0, pf1;
    if (j < NBLK1) {
        const float4* in4 = (const float4*)(input + (size_t)j * ROWS1 * H);
        pf0 = in4[tid]; pf1 = in4[tid + THR1];
    }

    const uint32_t wb = ws_a + u * 16;
    const uint32_t xb = xs_a + (s * 8) * (XS_PITCH * 4);

    for (; j < NBLK1; j += GRID1) {
        __syncthreads();   // previous tile's readers done
        *(float4*)(xs + r_st * XS_PITCH + kq * 4)        = pf0;
        *(float4*)(xs + (r_st + 16) * XS_PITCH + kq * 4) = pf1;
        __syncthreads();   // tile visible

        int jn = j + GRID1;
        if (jn < NBLK1) {   // prefetch next tile (hides DRAM under compute)
            const float4* in4 = (const float4*)(input + (size_t)jn * ROWS1 * H);
            pf0 = in4[tid]; pf1 = in4[tid + THR1];
        }

        u64 aR[8], aZ[8], aN[8];
        #pragma unroll
        for (int r = 0; r < 8; r++) {
            aR[r] = pack2(br, 0.f); aZ[r] = pack2(bz, 0.f); aN[r] = pack2(bn, 0.f);
        }

        #pragma unroll 2
        for (int kk = 0; kk < 32; kk++) {
            u64 wr0, wr1, wz0, wz1, wn0, wn1;
            const uint32_t wo = wb + kk * (G * 16);
            lds_v2u64(wr0, wr1, wo);
            lds_v2u64(wz0, wz1, wo + 128 * 16);
            lds_v2u64(wn0, wn1, wo + 256 * 16);
            #pragma unroll
            for (int r = 0; r < 8; r++) {
                u64 x0, x1;
                lds_v2u64(x0, x1, xb + r * (XS_PITCH * 4) + kk * 16);   // broadcast
                aR[r] = ffma2(x0, wr0, aR[r]); aR[r] = ffma2(x1, wr1, aR[r]);
                aZ[r] = ffma2(x0, wz0, aZ[r]); aZ[r] = ffma2(x1, wz1, aZ[r]);
                aN[r] = ffma2(x0, wn0, aN[r]); aN[r] = ffma2(x1, wn1, aN[r]);
            }
        }

        float* outp = g_xg + ((size_t)j * ROWS1 + s * 8) * G + u;
        #pragma unroll
        for (int r = 0; r < 8; r++) {
            float l, h2;
            unpack2(aR[r], l, h2); outp[(size_t)r * G]       = l + h2;
            unpack2(aZ[r], l, h2); outp[(size_t)r * G + 128] = l + h2;
            unpack2(aN[r], l, h2); outp[(size_t)r * G + 256] = l + h2;
        }
    }
}

// ---------------------------------------------------------------------------
// Phase 2: sequential recurrence + output projection.
// 128 CTAs x 256 threads; thread (u, s) owns unit u for rows s*4..s*4+3.
// ---------------------------------------------------------------------------
constexpr int THR2  = 256;
constexpr int SMEM2 = WS_BYTES + 8 * XS_PITCH * 4 + 8 * H * 4;   // 204928 B

__global__ void __launch_bounds__(THR2) gru_kernel(const float* __restrict__ initial_h,
                                                   const float* __restrict__ w_hh,
                                                   const float* __restrict__ b_hh,
                                                   const float* __restrict__ w_out,
                                                   const float* __restrict__ b_out,
                                                   float* __restrict__ out) {
    extern __shared__ char smem[];
    float4* ws4 = (float4*)smem;
    float*  hs  = (float*)(smem + WS_BYTES);                       // [8][132]
    float*  red = (float*)(smem + WS_BYTES + 8 * XS_PITCH * 4);    // [8][128]
    const uint32_t ws_a = smem_u32(smem);
    const uint32_t hs_a = ws_a + WS_BYTES;

    const int tid = threadIdx.x;
    const int u   = tid & 127;
    const int s   = tid >> 7;          // 0: rows 0-3, 1: rows 4-7
    const int b0  = blockIdx.x * 8;

    const float4* w4 = (const float4*)w_hh;
    for (int i = tid; i < G * 32; i += THR2) {
        int g = i >> 5, kk = i & 31;
        ws4[kk * G + g] = w4[g * 32 + kk];
    }
    const float br = b_hh[u], bz = b_hh[u + 128], bn = b_hh[u + 256];

    float hreg[4];
    #pragma unroll
    for (int r = 0; r < 4; r++) {
        int row = s * 4 + r;
        hreg[r] = initial_h[(size_t)(b0 + row) * H + u];
        hs[row * XS_PITCH + u] = hreg[r];
    }

    // prefetch xg for t = 0
    float cxR[4], cxZ[4], cxN[4];
    {
        const float* xg0 = g_xg + ((size_t)0 * BB + b0) * G + u;
        #pragma unroll
        for (int r = 0; r < 4; r++) {
            int row = s * 4 + r;
            cxR[r] = xg0[(size_t)row * G];
            cxZ[r] = xg0[(size_t)row * G + 128];
            cxN[r] = xg0[(size_t)row * G + 256];
        }
    }
    __syncthreads();

    const uint32_t wb = ws_a + u * 16;
    const uint32_t hb = hs_a + (s * 4) * (XS_PITCH * 4);

    for (int t = 0; t < TT; t++) {
        // prefetch next step's xg (clamped; hides DRAM stream)
        float nxR[4], nxZ[4], nxN[4];
        {
            int tn = (t + 1 < TT) ? (t + 1) : t;
            const float* xgn = g_xg + ((size_t)tn * BB + b0) * G + u;
            #pragma unroll
            for (int r = 0; r < 4; r++) {
                int row = s * 4 + r;
                nxR[r] = xgn[(size_t)row * G];
                nxZ[r] = xgn[(size_t)row * G + 128];
                nxN[r] = xgn[(size_t)row * G + 256];
            }
        }

        u64 aR[4], aZ[4], aN[4];
        #pragma unroll
        for (int r = 0; r < 4; r++) {
            aR[r] = pack2(cxR[r] + br, 0.f);   // fold x + bias into acc init
            aZ[r] = pack2(cxZ[r] + bz, 0.f);
            aN[r] = pack2(bn, 0.f);            // n gate: r * (h@Wn + bn) — keep separate
        }

        #pragma unroll 2
        for (int kk = 0; kk < 32; kk++) {
            u64 wr0, wr1, wz0, wz1, wn0, wn1;
            const uint32_t wo = wb + kk * (G * 16);
            lds_v2u64(wr0, wr1, wo);
            lds_v2u64(wz0, wz1, wo + 128 * 16);
            lds_v2u64(wn0, wn1, wo + 256 * 16);
            #pragma unroll
            for (int r = 0; r < 4; r++) {
                u64 x0, x1;
                lds_v2u64(x0, x1, hb + r * (XS_PITCH * 4) + kk * 16);   // broadcast
                aR[r] = ffma2(x0, wr0, aR[r]); aR[r] = ffma2(x1, wr1, aR[r]);
                aZ[r] = ffma2(x0, wz0, aZ[r]); aZ[r] = ffma2(x1, wz1, aZ[r]);
                aN[r] = ffma2(x0, wn0, aN[r]); aN[r] = ffma2(x1, wn1, aN[r]);
            }
        }

        // gates + state update (thread-local, no cross-thread comm)
        #pragma unroll
        for (int r = 0; r < 4; r++) {
            float l, h2;
            unpack2(aR[r], l, h2); float rg = sigf(l + h2);
            unpack2(aZ[r], l, h2); float zg = sigf(l + h2);
            unpack2(aN[r], l, h2); float ng = tanhf_fast(cxN[r] + rg * (l + h2));
            hreg[r] = (1.0f - zg) * ng + zg * hreg[r];
            cxR[r] = nxR[r]; cxZ[r] = nxZ[r]; cxN[r] = nxN[r];
        }

        __syncthreads();   // all matvec reads of hs done
        #pragma unroll
        for (int r = 0; r < 4; r++) hs[(s * 4 + r) * XS_PITCH + u] = hreg[r];
        __syncthreads();   // new h visible
    }

    // projection: out[b] = sum_u h[b][u]*w_out[u] + b_out (deterministic tree)
    const float wo = w_out[u];
    #pragma unroll
    for (int r = 0; r < 4; r++) red[(s * 4 + r) * H + u] = hreg[r] * wo;
    __syncthreads();
    for (int st = 64; st > 0; st >>= 1) {
        if (u < st) {
            #pragma unroll
            for (int r = 0; r < 4; r++)
                red[(s * 4 + r) * H + u] += red[(s * 4 + r) * H + u + st];
        }
        __syncthreads();
    }
    if (tid < 8) out[b0 + tid] = red[tid * H] + b_out[0];
}

// ---------------------------------------------------------------------------
// launch
// ---------------------------------------------------------------------------
extern "C" void kernel_launch(void* const* d_in, const int* in_sizes, int n_in,
                              void* d_out, int out_size) {
    const float* input     = (const float*)d_in[0];   // [T, B, H]
    const float* initial_h = (const float*)d_in[1];   // [B, H]
    const float* w_ih      = (const float*)d_in[2];   // [3H, H]
    const float* w_hh      = (const float*)d_in[3];   // [3H, H]
    const float* b_ih      = (const float*)d_in[4];   // [3H]
    const float* b_hh      = (const float*)d_in[5];   // [3H]
    const float* w_out     = (const float*)d_in[6];   // [1, H]
    const float* b_out     = (const float*)d_in[7];   // [1]
    float*       out       = (float*)d_out;           // [B, 1]

    (void)in_sizes; (void)n_in; (void)out_size;

    cudaFuncSetAttribute(xg_kernel,  cudaFuncAttributeMaxDynamicSharedMemorySize, SMEM1);
    cudaFuncSetAttribute(gru_kernel, cudaFuncAttributeMaxDynamicSharedMemorySize, SMEM2);

    xg_kernel<<<GRID1, THR1, SMEM1>>>(input, w_ih, b_ih);
    gru_kernel<<<BB / 8, THR2, SMEM2>>>(initial_h, w_hh, b_hh, w_out, b_out, out);
}